// round 16
// baseline (speedup 1.0000x reference)
#include <cuda_runtime.h>
#include <cuda_fp16.h>
#include <math.h>
#include <stdint.h>

#define Bz 8
#define Mz 512
#define DMz 1024
#define Hz 16
#define DHz 64
#define DFFz 4096
#define RAz 32
#define RFz 384
#define ROz 384
#define BMr (Bz*Mz)          // 4096
#define C3 (3*Hz*RAz)        // 1536
#define ZT (Bz*Hz)           // 128
#define LN_EPS 1e-12f

// ---------------- scratch (device globals) ----------------
// A-side: [M][K/2] u32 pairs along K. B-side: plain fp16 row-major [K][N/2].
__device__ uint32_t g_xh[BMr*512];
__device__ uint32_t g_wch[DMz*(C3/2)];           // [1024][768]
__device__ uint32_t g_Qh[ZT*Mz*32];              // [z][tok][dpair] (scaled by 1/8, +bq)
__device__ uint32_t g_Kh[ZT*Mz*32];              // [z][tok][dpair]
__device__ uint32_t g_Vh[ZT*Mz*32];              // [z][tok][dpair]
__device__ uint32_t g_ath[BMr*512];
__device__ uint32_t g_Uoh[DMz*(ROz/2)];
__device__ uint32_t g_Voh[ROz*(DMz/2)];
__device__ uint32_t g_U1h[DMz*(RFz/2)];
__device__ uint32_t g_V1h[RFz*(DFFz/2)];
__device__ uint32_t g_U2h[DFFz*(RFz/2)];
__device__ uint32_t g_V2h[RFz*(DMz/2)];
__device__ uint32_t g_t1h[BMr*192];
__device__ float    g_y1[BMr*DMz];
__device__ float    g_x1[BMr*DMz];
__device__ uint32_t g_x1h[BMr*512];
__device__ uint32_t g_mdh[BMr*192];
__device__ uint32_t g_hdh[(size_t)BMr*2048];
__device__ uint32_t g_t2h[BMr*192];
__device__ float    g_y2[BMr*DMz];

// ---------------- helpers ----------------
__device__ __forceinline__ float gelu_f(float x) {
    return 0.5f * x * (1.0f + erff(x * 0.70710678118654752440f));
}
__device__ __forceinline__ uint32_t cvt_pair(float x0, float x1) {
    __half2 hh = __halves2half2(__float2half_rn(x0), __float2half_rn(x1));
    return *(uint32_t*)&hh;
}
__device__ __forceinline__ void mma16(float* c, const uint32_t* a, const uint32_t* b) {
    asm volatile(
        "mma.sync.aligned.m16n8k16.row.col.f32.f16.f16.f32 "
        "{%0,%1,%2,%3}, {%4,%5,%6,%7}, {%8,%9}, {%0,%1,%2,%3};"
        : "+f"(c[0]), "+f"(c[1]), "+f"(c[2]), "+f"(c[3])
        : "r"(a[0]), "r"(a[1]), "r"(a[2]), "r"(a[3]), "r"(b[0]), "r"(b[1]));
}
__device__ __forceinline__ uint32_t smem_u32(const void* p) {
    return (uint32_t)__cvta_generic_to_shared(p);
}
__device__ __forceinline__ void ldsm4(uint32_t& r0, uint32_t& r1, uint32_t& r2,
                                      uint32_t& r3, uint32_t addr) {
    asm volatile("ldmatrix.sync.aligned.m8n8.x4.shared.b16 {%0,%1,%2,%3}, [%4];"
                 : "=r"(r0), "=r"(r1), "=r"(r2), "=r"(r3) : "r"(addr));
}
__device__ __forceinline__ void ldsm4t(uint32_t& r0, uint32_t& r1, uint32_t& r2,
                                       uint32_t& r3, uint32_t addr) {
    asm volatile("ldmatrix.sync.aligned.m8n8.x4.trans.shared.b16 {%0,%1,%2,%3}, [%4];"
                 : "=r"(r0), "=r"(r1), "=r"(r2), "=r"(r3) : "r"(addr));
}
__device__ __forceinline__ void cp16(uint32_t dst, const void* src) {
    asm volatile("cp.async.cg.shared.global [%0], [%1], 16;" :: "r"(dst), "l"(src));
}
#define CP_COMMIT() asm volatile("cp.async.commit_group;")
#define CP_WAIT1()  asm volatile("cp.async.wait_group 1;")

// ---------------- conversion kernels ----------------
__global__ void conv_x(const float* __restrict__ x) {
    int idx = blockIdx.x * blockDim.x + threadIdx.x;
    int row = idx >> 9, p = idx & 511;
    float2 v = *(const float2*)(x + (size_t)row * DMz + 2 * p);
    g_xh[idx] = cvt_pair(v.x, v.y);
}
__global__ void pack_w_split(const float* __restrict__ Pq, const float* __restrict__ Pk,
                             const float* __restrict__ Pv) {
    int idx = blockIdx.x * blockDim.x + threadIdx.x;   // 1024 * 768
    int d = idx / (C3 / 2), np = idx % (C3 / 2);
    float v[2];
#pragma unroll
    for (int u = 0; u < 2; u++) {
        int c = 2 * np + u;
        int j = c / 512, hr = c % 512, h = hr >> 5, r = hr & 31;
        const float* P = (j == 0) ? Pq : ((j == 1) ? Pk : Pv);
        v[u] = P[((size_t)h * DMz + d) * RAz + r];
    }
    g_wch[idx] = cvt_pair(v[0], v[1]);
}
// all six B-side weights in ONE kernel
__global__ void convAll(const float* __restrict__ Uo, const float* __restrict__ Vo,
                        const float* __restrict__ U1, const float* __restrict__ V1,
                        const float* __restrict__ U2, const float* __restrict__ V2) {
    int idx = blockIdx.x * blockDim.x + threadIdx.x;
    const float* W; uint32_t* dst; int N, base;
    if      (idx <  196608) { W = Uo; dst = g_Uoh; N = 384;  base = 0; }
    else if (idx <  393216) { W = Vo; dst = g_Voh; N = 1024; base = 196608; }
    else if (idx <  589824) { W = U1; dst = g_U1h; N = 384;  base = 393216; }
    else if (idx < 1376256) { W = V1; dst = g_V1h; N = 4096; base = 589824; }
    else if (idx < 2162688) { W = U2; dst = g_U2h; N = 384;  base = 1376256; }
    else if (idx < 2359296) { W = V2; dst = g_V2h; N = 1024; base = 2162688; }
    else return;
    int li = idx - base;
    int n2 = N >> 1;
    int k = li / n2, np = li % n2;
    float v0 = W[(size_t)k * N + 2 * np];
    float v1 = W[(size_t)k * N + 2 * np + 1];
    dst[li] = cvt_pair(v0, v1);
}

// =====================================================================
// fp16 GEMM with ldmatrix (unchanged from R15).
// =====================================================================
template <int CTAM, bool OF32, bool OSPL, int EPI>
__launch_bounds__(256, 2)
__global__ void hgemm(const uint32_t* __restrict__ Ah, const uint32_t* __restrict__ Bh,
                      float* __restrict__ Cf, uint32_t* __restrict__ Ch,
                      int N, int K, const float* __restrict__ bias) {
    constexpr int MT = CTAM / 32;
    __shared__ uint32_t Ash[3][CTAM][8];
    __shared__ uint32_t Bsh[3][16][64];

    int tid = threadIdx.x, lane = tid & 31, wid = tid >> 5;
    int warp_m = (wid >> 2) * (CTAM / 2);
    int warp_n = (wid & 3) * 32;
    int by = blockIdx.y, bx = blockIdx.x;
    int kp2 = K >> 1, n2 = N >> 1;
    int mq = lane >> 2, kq = lane & 3;
    int nk = K >> 4;
    int lt = lane >> 3, lr = lane & 7;

    auto load_stage = [&](int kt, int s) {
        if (tid < CTAM * 2) {
            int row = tid >> 1, hf = (tid & 1) * 4;
            int cc = hf ^ (row & 4);
            size_t so = (size_t)(by * CTAM + row) * kp2 + kt * 8 + hf;
            cp16(smem_u32(&Ash[s][row][cc]), Ah + so);
        }
        {
            int row = tid >> 4, ch = tid & 15;
            int cc = ch ^ ((row & 7) * 2);
            size_t so = (size_t)(kt * 16 + row) * n2 + bx * 64 + ch * 4;
            cp16(smem_u32(&Bsh[s][row][cc * 4]), Bh + so);
        }
    };

    float acc[MT][4][4];
#pragma unroll
    for (int i = 0; i < MT; i++)
#pragma unroll
        for (int j = 0; j < 4; j++)
#pragma unroll
            for (int t = 0; t < 4; t++) acc[i][j][t] = 0.f;

    load_stage(0, 0); CP_COMMIT();
    load_stage(1, 1); CP_COMMIT();

    for (int kt = 0; kt < nk; kt++) {
        CP_WAIT1();
        __syncthreads();
        int s = kt % 3;
        uint32_t fb[4][2];
#pragma unroll
        for (int p = 0; p < 2; p++) {
            int krow = (lt & 1) * 8 + lr;
            int chIdx = (warp_n >> 3) + p * 2 + (lt >> 1);
            uint32_t addr = smem_u32(&Bsh[s][krow][4 * (chIdx ^ ((krow & 7) * 2))]);
            ldsm4t(fb[2 * p][0], fb[2 * p][1], fb[2 * p + 1][0], fb[2 * p + 1][1], addr);
        }
#pragma unroll
        for (int mt = 0; mt < MT; mt++) {
            int row = warp_m + mt * 16 + (lt & 1) * 8 + lr;
            uint32_t addr = smem_u32(&Ash[s][row][((lt >> 1) * 4) ^ (row & 4)]);
            uint32_t fa[4];
            ldsm4(fa[0], fa[1], fa[2], fa[3], addr);
#pragma unroll
            for (int nt = 0; nt < 4; nt++) mma16(acc[mt][nt], fa, fb[nt]);
        }
        if (kt + 2 < nk) load_stage(kt + 2, (kt + 2) % 3);
        CP_COMMIT();
    }

#pragma unroll
    for (int mt = 0; mt < MT; mt++)
#pragma unroll
        for (int nt = 0; nt < 4; nt++) {
            int row = by * CTAM + warp_m + mt * 16 + mq;
            int col = bx * 128 + warp_n + nt * 8 + kq * 2;
            float v0 = acc[mt][nt][0], v1 = acc[mt][nt][1];
            float v2 = acc[mt][nt][2], v3 = acc[mt][nt][3];
            if (EPI >= 1) {
                float b0 = bias[col], b1 = bias[col + 1];
                v0 += b0; v1 += b1; v2 += b0; v3 += b1;
            }
            if (EPI == 2) {
                v0 = gelu_f(v0); v1 = gelu_f(v1); v2 = gelu_f(v2); v3 = gelu_f(v3);
            }
            if (OF32) {
                *(float2*)(Cf + (size_t)row * N + col) = make_float2(v0, v1);
                *(float2*)(Cf + (size_t)(row + 8) * N + col) = make_float2(v2, v3);
            }
            if (OSPL) {
                size_t o = (size_t)row * (N >> 1) + (col >> 1);
                Ch[o] = cvt_pair(v0, v1);
                o = (size_t)(row + 8) * (N >> 1) + (col >> 1);
                Ch[o] = cvt_pair(v2, v3);
            }
        }
}

// =====================================================================
// qkv GEMM with FUSED rank-32 expansion epilogue.
// Main loop: T = x @ Wcat (128x128 tile). Each warp's 32 cols = one head's
// 32 r values. Epilogue: out[64 tok][64 d] = Tw @ Vj[h] (+bias), written
// tok-major to g_Qh/g_Kh/g_Vh. Q gets (val+bq)*0.125 (scale folded).
// =====================================================================
__launch_bounds__(256, 2)
__global__ void hgemm_qkv(const uint32_t* __restrict__ Ah, const uint32_t* __restrict__ Bh,
                          const float* __restrict__ Vq, const float* __restrict__ Vk,
                          const float* __restrict__ Vv, const float* __restrict__ bq,
                          const float* __restrict__ bk, const float* __restrict__ bv) {
    __shared__ uint32_t Ash[3][128][8];
    __shared__ uint32_t Bsh[3][16][64];
    __shared__ uint32_t Vjs[4][32][32];     // [hloc][r][dpair], swz ch^(r&7)

    int tid = threadIdx.x, lane = tid & 31, wid = tid >> 5;
    int warp_m = (wid >> 2) * 64;
    int warp_n = (wid & 3) * 32;
    int by = blockIdx.y, bx = blockIdx.x;
    const int K = DMz, N = C3;
    int kp2 = K >> 1, n2 = N >> 1;
    int mq = lane >> 2, kq = lane & 3;
    int nk = K >> 4;
    int lt = lane >> 3, lr = lane & 7;

    int j = bx >> 2;
    const float* Vm = (j == 0) ? Vq : ((j == 1) ? Vk : Vv);
    const float* bm = (j == 0) ? bq : ((j == 1) ? bk : bv);

    // load Vj tiles for this CTA's 4 heads (visible after first __syncthreads)
    for (int i = tid; i < 4096; i += 256) {
        int hl = i >> 10, r = (i >> 5) & 31, dp = i & 31;
        int hg = (bx & 3) * 4 + hl;
        const float* src = Vm + ((size_t)hg * RAz + r) * DHz + 2 * dp;
        Vjs[hl][r][4 * ((dp >> 2) ^ (r & 7)) + (dp & 3)] = cvt_pair(src[0], src[1]);
    }

    auto load_stage = [&](int kt, int s) {
        {
            int row = tid >> 1, hf = (tid & 1) * 4;
            int cc = hf ^ (row & 4);
            size_t so = (size_t)(by * 128 + row) * kp2 + kt * 8 + hf;
            cp16(smem_u32(&Ash[s][row][cc]), Ah + so);
        }
        {
            int row = tid >> 4, ch = tid & 15;
            int cc = ch ^ ((row & 7) * 2);
            size_t so = (size_t)(kt * 16 + row) * n2 + bx * 64 + ch * 4;
            cp16(smem_u32(&Bsh[s][row][cc * 4]), Bh + so);
        }
    };

    float acc[4][4][4];
#pragma unroll
    for (int i = 0; i < 4; i++)
#pragma unroll
        for (int jj = 0; jj < 4; jj++)
#pragma unroll
            for (int t = 0; t < 4; t++) acc[i][jj][t] = 0.f;

    load_stage(0, 0); CP_COMMIT();
    load_stage(1, 1); CP_COMMIT();

    for (int kt = 0; kt < nk; kt++) {
        CP_WAIT1();
        __syncthreads();
        int s = kt % 3;
        uint32_t fb[4][2];
#pragma unroll
        for (int p = 0; p < 2; p++) {
            int krow = (lt & 1) * 8 + lr;
            int chIdx = (warp_n >> 3) + p * 2 + (lt >> 1);
            uint32_t addr = smem_u32(&Bsh[s][krow][4 * (chIdx ^ ((krow & 7) * 2))]);
            ldsm4t(fb[2 * p][0], fb[2 * p][1], fb[2 * p + 1][0], fb[2 * p + 1][1], addr);
        }
#pragma unroll
        for (int mt = 0; mt < 4; mt++) {
            int row = warp_m + mt * 16 + (lt & 1) * 8 + lr;
            uint32_t addr = smem_u32(&Ash[s][row][((lt >> 1) * 4) ^ (row & 4)]);
            uint32_t fa[4];
            ldsm4(fa[0], fa[1], fa[2], fa[3], addr);
#pragma unroll
            for (int nt = 0; nt < 4; nt++) mma16(acc[mt][nt], fa, fb[nt]);
        }
        if (kt + 2 < nk) load_stage(kt + 2, (kt + 2) % 3);
        CP_COMMIT();
    }

    // ---- fused expansion epilogue ----
    int hl = wid & 3;
    int hg = (bx & 3) * 4 + hl;
    int z = (by >> 2) * Hz + hg;
    uint32_t* dst = (j == 0) ? g_Qh : ((j == 1) ? g_Kh : g_Vh);
    float scale = (j == 0) ? 0.125f : 1.0f;
    int m_base = (by & 3) * 128 + warp_m;

#pragma unroll
    for (int mt = 0; mt < 4; mt++) {
        int m = m_base + mt * 16 + mq;
#pragma unroll
        for (int ntp = 0; ntp < 4; ntp++) {
            float oq0[4] = {0.f, 0.f, 0.f, 0.f};
            float oq1[4] = {0.f, 0.f, 0.f, 0.f};
#pragma unroll
            for (int kc = 0; kc < 2; kc++) {
                uint32_t fa[4];
                fa[0] = cvt_pair(acc[mt][2 * kc][0],     acc[mt][2 * kc][1]);
                fa[1] = cvt_pair(acc[mt][2 * kc][2],     acc[mt][2 * kc][3]);
                fa[2] = cvt_pair(acc[mt][2 * kc + 1][0], acc[mt][2 * kc + 1][1]);
                fa[3] = cvt_pair(acc[mt][2 * kc + 1][2], acc[mt][2 * kc + 1][3]);
                int trow = kc * 16 + (lt & 1) * 8 + lr;
                int chk = ntp * 2 + (lt >> 1);
                uint32_t addr = smem_u32(&Vjs[hl][trow][4 * (chk ^ (trow & 7))]);
                uint32_t b0, b1, b2, b3;
                ldsm4t(b0, b1, b2, b3, addr);
                uint32_t fb0[2] = {b0, b1}, fb1[2] = {b2, b3};
                mma16(oq0, fa, fb0);
                mma16(oq1, fa, fb1);
            }
#pragma unroll
            for (int half = 0; half < 2; half++) {
                int nt = 2 * ntp + half;
                float* oq = half ? oq1 : oq0;
                int d = nt * 8 + kq * 2;
                float b0 = bm[hg * DHz + d], b1 = bm[hg * DHz + d + 1];
                size_t o = ((size_t)z * Mz + m) * 32 + (d >> 1);
                dst[o] = cvt_pair((oq[0] + b0) * scale, (oq[1] + b1) * scale);
                o = ((size_t)z * Mz + m + 8) * 32 + (d >> 1);
                dst[o] = cvt_pair((oq[2] + b0) * scale, (oq[3] + b1) * scale);
            }
        }
    }
}

// =====================================================================
// Fused flash attention. Q/K/V all tok-major [tok][dpair].
// S-loop: ldsm4 non-trans on K. PV-loop: ldsm4t on V. Scale folded into Q.
// =====================================================================
#define FLASH_SMEM_BYTES 83968
__launch_bounds__(256, 1)
__global__ void hflash(const float* __restrict__ mask) {
    extern __shared__ uint32_t dsm[];
    uint32_t* Qh = dsm;                               // [128][32]
    uint32_t* Khs[2] = {dsm + 4096,  dsm + 8192};     // [128 tok][32 u32] each
    uint32_t* Vhs[2] = {dsm + 12288, dsm + 16384};    // [128 tok][32 u32] each
    float* mk = (float*)(dsm + 20480);                // [512]

    int tid = threadIdx.x, lane = tid & 31, w = tid >> 5;
    int mq = lane >> 2, kq = lane & 3;
    int lt = lane >> 3, lr = lane & 7;
    int by = blockIdx.x, z = blockIdx.y;
    int b = z >> 4, h = z & 15;

    const uint32_t* Qhb = g_Qh + (size_t)z * Mz * 32;
    const uint32_t* Khb = g_Kh + (size_t)z * Mz * 32;
    const uint32_t* Vhb = g_Vh + (size_t)z * Mz * 32;

    {
        float2 mv = *(const float2*)(mask + (size_t)b * Mz + tid * 2);
        *(float2*)(mk + tid * 2) = mv;
    }

    auto load_kv = [&](int j, int s) {
#pragma unroll
        for (int i = 0; i < 4; i++) {
            int g = tid + i * 256;
            int row = g >> 3, ch = g & 7;
            int cc = ch ^ (row & 7);
            cp16(smem_u32(&Khs[s][row * 32 + cc * 4]),
                 Khb + (size_t)(j * 128 + row) * 32 + ch * 4);
        }
#pragma unroll
        for (int i = 0; i < 4; i++) {
            int g = tid + i * 256;
            int row = g >> 3, ch = g & 7;
            int cc = ch ^ (row & 7);
            cp16(smem_u32(&Vhs[s][row * 32 + cc * 4]),
                 Vhb + (size_t)(j * 128 + row) * 32 + ch * 4);
        }
    };

#pragma unroll
    for (int i = 0; i < 4; i++) {
        int g = tid + i * 256;
        int row = g >> 3, q0 = (g & 7) * 4;
        int cc = q0 ^ ((row & 7) * 4);
        size_t so = (size_t)(by * 128 + row) * 32 + q0;
        cp16(smem_u32(&Qh[row * 32 + cc]), Qhb + so);
    }
    load_kv(0, 0); CP_COMMIT();
    load_kv(1, 1); CP_COMMIT();

    float sacc[16][4];
    float oacc[8][4];
#pragma unroll
    for (int i = 0; i < 8; i++)
#pragma unroll
        for (int t = 0; t < 4; t++) oacc[i][t] = 0.f;
    float rmax0 = -1e30f, rmax1 = -1e30f;
    float rsum0 = 0.f, rsum1 = 0.f;
    uint32_t qh[4][4];

    for (int j = 0; j < 4; j++) {
        CP_WAIT1();
        __syncthreads();
        int s = j & 1;
        if (j == 0) {
            int r0 = w * 16 + mq, r1 = r0 + 8;
#pragma unroll
            for (int c = 0; c < 4; c++) {
                int p0 = (c * 8 + kq) ^ (mq * 4);
                int p1 = (c * 8 + 4 + kq) ^ (mq * 4);
                qh[c][0] = Qh[r0 * 32 + p0];
                qh[c][1] = Qh[r1 * 32 + p0];
                qh[c][2] = Qh[r0 * 32 + p1];
                qh[c][3] = Qh[r1 * 32 + p1];
            }
        }
        // ---- S = Q K^T (ldsm4 non-trans on tok-major K) ----
#pragma unroll
        for (int nt = 0; nt < 16; nt++)
#pragma unroll
            for (int t = 0; t < 4; t++) sacc[nt][t] = 0.f;
#pragma unroll
        for (int c = 0; c < 4; c++) {
#pragma unroll
            for (int ntp = 0; ntp < 8; ntp++) {
                int tokrow = ntp * 16 + (lt & 1) * 8 + lr;
                int chk = c * 2 + (lt >> 1);
                uint32_t addr = smem_u32(&Khs[s][tokrow * 32 + 4 * (chk ^ (tokrow & 7))]);
                uint32_t b0, b1, b2, b3;
                ldsm4(b0, b1, b2, b3, addr);
                uint32_t fb0[2] = {b0, b2}, fb1[2] = {b1, b3};
                mma16(sacc[2 * ntp], qh[c], fb0);
                mma16(sacc[2 * ntp + 1], qh[c], fb1);
            }
        }
        // ---- mask + online softmax (scale pre-folded into Q) ----
        float tm0 = -1e30f, tm1 = -1e30f;
#pragma unroll
        for (int nt = 0; nt < 16; nt++) {
            int n0 = j * 128 + nt * 8 + kq * 2;
            float m0 = mk[n0], m1 = mk[n0 + 1];
            sacc[nt][0] += m0;
            sacc[nt][1] += m1;
            sacc[nt][2] += m0;
            sacc[nt][3] += m1;
            tm0 = fmaxf(tm0, fmaxf(sacc[nt][0], sacc[nt][1]));
            tm1 = fmaxf(tm1, fmaxf(sacc[nt][2], sacc[nt][3]));
        }
        tm0 = fmaxf(tm0, __shfl_xor_sync(0xffffffffu, tm0, 1));
        tm0 = fmaxf(tm0, __shfl_xor_sync(0xffffffffu, tm0, 2));
        tm1 = fmaxf(tm1, __shfl_xor_sync(0xffffffffu, tm1, 1));
        tm1 = fmaxf(tm1, __shfl_xor_sync(0xffffffffu, tm1, 2));
        float nm0 = fmaxf(rmax0, tm0), nm1 = fmaxf(rmax1, tm1);
        float f0 = __expf(rmax0 - nm0), f1 = __expf(rmax1 - nm1);
        rmax0 = nm0; rmax1 = nm1;
        rsum0 *= f0; rsum1 *= f1;
#pragma unroll
        for (int nt = 0; nt < 8; nt++) {
            oacc[nt][0] *= f0; oacc[nt][1] *= f0;
            oacc[nt][2] *= f1; oacc[nt][3] *= f1;
        }
        float ps0 = 0.f, ps1 = 0.f;
#pragma unroll
        for (int nt = 0; nt < 16; nt++) {
            sacc[nt][0] = __expf(sacc[nt][0] - nm0);
            sacc[nt][1] = __expf(sacc[nt][1] - nm0);
            sacc[nt][2] = __expf(sacc[nt][2] - nm1);
            sacc[nt][3] = __expf(sacc[nt][3] - nm1);
            ps0 += sacc[nt][0] + sacc[nt][1];
            ps1 += sacc[nt][2] + sacc[nt][3];
        }
        rsum0 += ps0; rsum1 += ps1;
        // ---- O += P V (ldsm4t on tok-major V) ----
#pragma unroll
        for (int cc = 0; cc < 8; cc++) {
            uint32_t pah[4];
            pah[0] = cvt_pair(sacc[2 * cc][0],     sacc[2 * cc][1]);
            pah[1] = cvt_pair(sacc[2 * cc][2],     sacc[2 * cc][3]);
            pah[2] = cvt_pair(sacc[2 * cc + 1][0], sacc[2 * cc + 1][1]);
            pah[3] = cvt_pair(sacc[2 * cc + 1][2], sacc[2 * cc + 1][3]);
#pragma unroll
            for (int ntp = 0; ntp < 4; ntp++) {
                int trow = cc * 16 + (lt & 1) * 8 + lr;
                int chk = ntp * 2 + (lt >> 1);
                uint32_t addr = smem_u32(&Vhs[s][trow * 32 + 4 * (chk ^ (trow & 7))]);
                uint32_t b0, b1, b2, b3;
                ldsm4t(b0, b1, b2, b3, addr);
                uint32_t fb0[2] = {b0, b1}, fb1[2] = {b2, b3};
                mma16(oacc[2 * ntp], pah, fb0);
                mma16(oacc[2 * ntp + 1], pah, fb1);
            }
        }
        __syncthreads();
        if (j + 2 < 4) load_kv(j + 2, s);
        CP_COMMIT();
    }

    // ---- epilogue ----
    rsum0 += __shfl_xor_sync(0xffffffffu, rsum0, 1);
    rsum0 += __shfl_xor_sync(0xffffffffu, rsum0, 2);
    rsum1 += __shfl_xor_sync(0xffffffffu, rsum1, 1);
    rsum1 += __shfl_xor_sync(0xffffffffu, rsum1, 2);
    float inv0 = 1.0f / rsum0, inv1 = 1.0f / rsum1;
    int m0 = by * 128 + w * 16 + mq;
#pragma unroll
    for (int nt = 0; nt < 8; nt++) {
        int d = nt * 8 + kq * 2;
        int colp = (h * DHz + d) >> 1;
        size_t o = (size_t)(b * Mz + m0) * 512 + colp;
        g_ath[o] = cvt_pair(oacc[nt][0] * inv0, oacc[nt][1] * inv0);
        o = (size_t)(b * Mz + m0 + 8) * 512 + colp;
        g_ath[o] = cvt_pair(oacc[nt][2] * inv1, oacc[nt][3] * inv1);
    }
}

// ---------------- residual + LayerNorm ----------------
template <bool SPLIT>
__launch_bounds__(256)
__global__ void ln_k(const float* __restrict__ a, const float* __restrict__ r,
                     const float* __restrict__ g, const float* __restrict__ bb,
                     float* __restrict__ out) {
    __shared__ float sh[8];
    int row = blockIdx.x;
    int tid = threadIdx.x;
    int lane = tid & 31, warp = tid >> 5;
    int c = tid * 4;
    float4 xa = *(const float4*)(a + (size_t)row * DMz + c);
    float4 ya = *(const float4*)(r + (size_t)row * DMz + c);
    float v[4] = {xa.x + ya.x, xa.y + ya.y, xa.z + ya.z, xa.w + ya.w};
    float s = v[0] + v[1] + v[2] + v[3];
#pragma unroll
    for (int o = 16; o > 0; o >>= 1) s += __shfl_xor_sync(0xffffffffu, s, o);
    if (lane == 0) sh[warp] = s;
    __syncthreads();
    if (warp == 0) {
        float t = (lane < 8) ? sh[lane] : 0.f;
#pragma unroll
        for (int o = 4; o > 0; o >>= 1) t += __shfl_xor_sync(0xffffffffu, t, o);
        if (lane == 0) sh[0] = t;
    }
    __syncthreads();
    float mu = sh[0] * (1.0f / DMz);
    __syncthreads();

    float q = 0.f;
#pragma unroll
    for (int i = 0; i < 4; i++) {
        float d = v[i] - mu;
        q += d * d;
    }
#pragma unroll
    for (int o = 16; o > 0; o >>= 1) q += __shfl_xor_sync(0xffffffffu, q, o);
    if (lane == 0) sh[warp] = q;
    __syncthreads();
    if (warp == 0) {
        float t = (lane < 8) ? sh[lane] : 0.f;
#pragma unroll
        for (int o = 4; o > 0; o >>= 1) t += __shfl_xor_sync(0xffffffffu, t, o);
        if (lane == 0) sh[0] = t;
    }
    __syncthreads();
    float var = sh[0] * (1.0f / DMz);
    float rs = rsqrtf(var + LN_EPS);
    float4 gg = *(const float4*)(g + c);
    float4 bbv = *(const float4*)(bb + c);
    float o0 = (v[0] - mu) * rs * gg.x + bbv.x;
    float o1 = (v[1] - mu) * rs * gg.y + bbv.y;
    float o2 = (v[2] - mu) * rs * gg.z + bbv.z;
    float o3 = (v[3] - mu) * rs * gg.w + bbv.w;
    *(float4*)(out + (size_t)row * DMz + c) = make_float4(o0, o1, o2, o3);
    if (SPLIT) {
        size_t o = (size_t)row * 512 + (c >> 1);
        g_x1h[o] = cvt_pair(o0, o1);
        g_x1h[o + 1] = cvt_pair(o2, o3);
    }
}

// ---------------- launch ----------------
extern "C" void kernel_launch(void* const* d_in, const int* in_sizes, int n_in,
                              void* d_out, int out_size) {
    const float* x    = (const float*)d_in[0];
    const float* mask = (const float*)d_in[1];
    const float* Pq   = (const float*)d_in[2];
    const float* Vq   = (const float*)d_in[3];
    const float* Pk   = (const float*)d_in[4];
    const float* Vk   = (const float*)d_in[5];
    const float* Pv   = (const float*)d_in[6];
    const float* Vv   = (const float*)d_in[7];
    const float* bq   = (const float*)d_in[8];
    const float* bk   = (const float*)d_in[9];
    const float* bv   = (const float*)d_in[10];
    const float* Uo   = (const float*)d_in[11];
    const float* Vo   = (const float*)d_in[12];
    const float* bo   = (const float*)d_in[13];
    const float* U1   = (const float*)d_in[14];
    const float* V1   = (const float*)d_in[15];
    const float* b1   = (const float*)d_in[16];
    const float* U2   = (const float*)d_in[17];
    const float* V2   = (const float*)d_in[18];
    const float* b2   = (const float*)d_in[19];
    const float* ln1g = (const float*)d_in[20];
    const float* ln1b = (const float*)d_in[21];
    const float* ln2g = (const float*)d_in[22];
    const float* ln2b = (const float*)d_in[23];
    float* out = (float*)d_out;

#define SYM(p, s) cudaGetSymbolAddress((void**)&p, s)
    uint32_t *xh, *wch, *Uoh, *Voh, *U1h, *V1h, *U2h, *V2h;
    uint32_t *ath, *t1h, *x1h, *mdh, *hdh, *t2h;
    float *y1, *x1, *y2;
    SYM(xh, g_xh); SYM(wch, g_wch);
    SYM(Uoh, g_Uoh); SYM(Voh, g_Voh);
    SYM(U1h, g_U1h); SYM(V1h, g_V1h);
    SYM(U2h, g_U2h); SYM(V2h, g_V2h);
    SYM(ath, g_ath); SYM(t1h, g_t1h);
    SYM(x1h, g_x1h); SYM(mdh, g_mdh);
    SYM(hdh, g_hdh); SYM(t2h, g_t2h);
    SYM(y1, g_y1); SYM(x1, g_x1); SYM(y2, g_y2);
#undef SYM

    cudaFuncSetAttribute(hflash, cudaFuncAttributeMaxDynamicSharedMemorySize,
                         FLASH_SMEM_BYTES);

    // operand conversion (3 launches)
    conv_x<<<BMr * 512 / 256, 256>>>(x);
    pack_w_split<<<DMz * (C3 / 2) / 256, 256>>>(Pq, Pk, Pv);
    convAll<<<(2359296 + 255) / 256, 256>>>(Uo, Vo, U1, V1, U2, V2);

    // qkv: GEMM + fused rank-32 expansion (writes Q/K/V directly)
    hgemm_qkv<<<dim3(C3 / 128, BMr / 128), 256>>>(xh, wch, Vq, Vk, Vv, bq, bk, bv);

    // fused attention
    hflash<<<dim3(Mz / 128, ZT), 256, FLASH_SMEM_BYTES>>>(mask);

    // output projection + LN1
    hgemm<64, false, true, 0><<<dim3(ROz / 128, BMr / 64), 256>>>(
        ath, Uoh, nullptr, t1h, ROz, DMz, nullptr);
    hgemm<128, true, false, 1><<<dim3(DMz / 128, BMr / 128), 256>>>(
        t1h, Voh, y1, nullptr, DMz, ROz, bo);
    ln_k<true><<<BMr, 256>>>(x, y1, ln1g, ln1b, x1);

    // FFN
    hgemm<64, false, true, 0><<<dim3(RFz / 128, BMr / 64), 256>>>(
        x1h, U1h, nullptr, mdh, RFz, DMz, nullptr);
    hgemm<128, false, true, 2><<<dim3(DFFz / 128, BMr / 128), 256>>>(
        mdh, V1h, nullptr, hdh, DFFz, RFz, b1);
    hgemm<64, false, true, 0><<<dim3(RFz / 128, BMr / 64), 256>>>(
        hdh, U2h, nullptr, t2h, RFz, DFFz, nullptr);
    hgemm<128, true, false, 1><<<dim3(DMz / 128, BMr / 128), 256>>>(
        t2h, V2h, y2, nullptr, DMz, RFz, b2);

    // LN2 -> out
    ln_k<false><<<BMr, 256>>>(x1, y2, ln2g, ln2b, out);
}

// round 17
// speedup vs baseline: 1.2623x; 1.2623x over previous
#include <cuda_runtime.h>
#include <cuda_fp16.h>
#include <math.h>
#include <stdint.h>

#define Bz 8
#define Mz 512
#define DMz 1024
#define Hz 16
#define DHz 64
#define DFFz 4096
#define RAz 32
#define RFz 384
#define ROz 384
#define BMr (Bz*Mz)          // 4096
#define C3 (3*Hz*RAz)        // 1536
#define ZT (Bz*Hz)           // 128
#define LN_EPS 1e-12f

// ---------------- scratch (device globals) ----------------
// A-side: [M][K/2] u32 pairs along K. B-side: plain fp16 row-major [K][N/2].
__device__ uint32_t g_xh[BMr*512];
__device__ uint32_t g_wch[DMz*(C3/2)];           // [1024][768]
__device__ uint32_t g_Th[BMr*768];               // T fp16 pairs [4096][768]
__device__ uint32_t g_Qh[ZT*Mz*32];              // [z][tok][dpair] (scaled 1/8, +bq)
__device__ uint32_t g_Kh[ZT*Mz*32];              // [z][tok][dpair]
__device__ uint32_t g_Vh[ZT*Mz*32];              // [z][tok][dpair]
__device__ uint32_t g_ath[BMr*512];
__device__ uint32_t g_Uoh[DMz*(ROz/2)];
__device__ uint32_t g_Voh[ROz*(DMz/2)];
__device__ uint32_t g_U1h[DMz*(RFz/2)];
__device__ uint32_t g_V1h[RFz*(DFFz/2)];
__device__ uint32_t g_U2h[DFFz*(RFz/2)];
__device__ uint32_t g_V2h[RFz*(DMz/2)];
__device__ uint32_t g_t1h[BMr*192];
__device__ float    g_y1[BMr*DMz];
__device__ float    g_x1[BMr*DMz];
__device__ uint32_t g_x1h[BMr*512];
__device__ uint32_t g_mdh[BMr*192];
__device__ uint32_t g_hdh[(size_t)BMr*2048];
__device__ uint32_t g_t2h[BMr*192];
__device__ float    g_y2[BMr*DMz];

// ---------------- helpers ----------------
__device__ __forceinline__ float gelu_f(float x) {
    return 0.5f * x * (1.0f + erff(x * 0.70710678118654752440f));
}
__device__ __forceinline__ uint32_t cvt_pair(float x0, float x1) {
    __half2 hh = __halves2half2(__float2half_rn(x0), __float2half_rn(x1));
    return *(uint32_t*)&hh;
}
__device__ __forceinline__ void mma16(float* c, const uint32_t* a, const uint32_t* b) {
    asm volatile(
        "mma.sync.aligned.m16n8k16.row.col.f32.f16.f16.f32 "
        "{%0,%1,%2,%3}, {%4,%5,%6,%7}, {%8,%9}, {%0,%1,%2,%3};"
        : "+f"(c[0]), "+f"(c[1]), "+f"(c[2]), "+f"(c[3])
        : "r"(a[0]), "r"(a[1]), "r"(a[2]), "r"(a[3]), "r"(b[0]), "r"(b[1]));
}
__device__ __forceinline__ uint32_t smem_u32(const void* p) {
    return (uint32_t)__cvta_generic_to_shared(p);
}
__device__ __forceinline__ void ldsm4(uint32_t& r0, uint32_t& r1, uint32_t& r2,
                                      uint32_t& r3, uint32_t addr) {
    asm volatile("ldmatrix.sync.aligned.m8n8.x4.shared.b16 {%0,%1,%2,%3}, [%4];"
                 : "=r"(r0), "=r"(r1), "=r"(r2), "=r"(r3) : "r"(addr));
}
__device__ __forceinline__ void ldsm4t(uint32_t& r0, uint32_t& r1, uint32_t& r2,
                                       uint32_t& r3, uint32_t addr) {
    asm volatile("ldmatrix.sync.aligned.m8n8.x4.trans.shared.b16 {%0,%1,%2,%3}, [%4];"
                 : "=r"(r0), "=r"(r1), "=r"(r2), "=r"(r3) : "r"(addr));
}
__device__ __forceinline__ void cp16(uint32_t dst, const void* src) {
    asm volatile("cp.async.cg.shared.global [%0], [%1], 16;" :: "r"(dst), "l"(src));
}
#define CP_COMMIT() asm volatile("cp.async.commit_group;")
#define CP_WAIT1()  asm volatile("cp.async.wait_group 1;")

// ---------------- conversion kernels ----------------
__global__ void conv_x(const float* __restrict__ x) {
    int idx = blockIdx.x * blockDim.x + threadIdx.x;
    int row = idx >> 9, p = idx & 511;
    float2 v = *(const float2*)(x + (size_t)row * DMz + 2 * p);
    g_xh[idx] = cvt_pair(v.x, v.y);
}
__global__ void pack_w_split(const float* __restrict__ Pq, const float* __restrict__ Pk,
                             const float* __restrict__ Pv) {
    int idx = blockIdx.x * blockDim.x + threadIdx.x;   // 1024 * 768
    int d = idx / (C3 / 2), np = idx % (C3 / 2);
    float v[2];
#pragma unroll
    for (int u = 0; u < 2; u++) {
        int c = 2 * np + u;
        int j = c / 512, hr = c % 512, h = hr >> 5, r = hr & 31;
        const float* P = (j == 0) ? Pq : ((j == 1) ? Pk : Pv);
        v[u] = P[((size_t)h * DMz + d) * RAz + r];
    }
    g_wch[idx] = cvt_pair(v[0], v[1]);
}
// all six B-side weights in ONE kernel
__global__ void convAll(const float* __restrict__ Uo, const float* __restrict__ Vo,
                        const float* __restrict__ U1, const float* __restrict__ V1,
                        const float* __restrict__ U2, const float* __restrict__ V2) {
    int idx = blockIdx.x * blockDim.x + threadIdx.x;
    const float* W; uint32_t* dst; int N, base;
    if      (idx <  196608) { W = Uo; dst = g_Uoh; N = 384;  base = 0; }
    else if (idx <  393216) { W = Vo; dst = g_Voh; N = 1024; base = 196608; }
    else if (idx <  589824) { W = U1; dst = g_U1h; N = 384;  base = 393216; }
    else if (idx < 1376256) { W = V1; dst = g_V1h; N = 4096; base = 589824; }
    else if (idx < 2162688) { W = U2; dst = g_U2h; N = 384;  base = 1376256; }
    else if (idx < 2359296) { W = V2; dst = g_V2h; N = 1024; base = 2162688; }
    else return;
    int li = idx - base;
    int n2 = N >> 1;
    int k = li / n2, np = li % n2;
    float v0 = W[(size_t)k * N + 2 * np];
    float v1 = W[(size_t)k * N + 2 * np + 1];
    dst[li] = cvt_pair(v0, v1);
}

// =====================================================================
// fp16 GEMM with ldmatrix (R15 design, unchanged).
// =====================================================================
template <int CTAM, bool OF32, bool OSPL, int EPI>
__launch_bounds__(256, 2)
__global__ void hgemm(const uint32_t* __restrict__ Ah, const uint32_t* __restrict__ Bh,
                      float* __restrict__ Cf, uint32_t* __restrict__ Ch,
                      int N, int K, const float* __restrict__ bias) {
    constexpr int MT = CTAM / 32;
    __shared__ uint32_t Ash[3][CTAM][8];
    __shared__ uint32_t Bsh[3][16][64];

    int tid = threadIdx.x, lane = tid & 31, wid = tid >> 5;
    int warp_m = (wid >> 2) * (CTAM / 2);
    int warp_n = (wid & 3) * 32;
    int by = blockIdx.y, bx = blockIdx.x;
    int kp2 = K >> 1, n2 = N >> 1;
    int mq = lane >> 2, kq = lane & 3;
    int nk = K >> 4;
    int lt = lane >> 3, lr = lane & 7;

    auto load_stage = [&](int kt, int s) {
        if (tid < CTAM * 2) {
            int row = tid >> 1, hf = (tid & 1) * 4;
            int cc = hf ^ (row & 4);
            size_t so = (size_t)(by * CTAM + row) * kp2 + kt * 8 + hf;
            cp16(smem_u32(&Ash[s][row][cc]), Ah + so);
        }
        {
            int row = tid >> 4, ch = tid & 15;
            int cc = ch ^ ((row & 7) * 2);
            size_t so = (size_t)(kt * 16 + row) * n2 + bx * 64 + ch * 4;
            cp16(smem_u32(&Bsh[s][row][cc * 4]), Bh + so);
        }
    };

    float acc[MT][4][4];
#pragma unroll
    for (int i = 0; i < MT; i++)
#pragma unroll
        for (int j = 0; j < 4; j++)
#pragma unroll
            for (int t = 0; t < 4; t++) acc[i][j][t] = 0.f;

    load_stage(0, 0); CP_COMMIT();
    load_stage(1, 1); CP_COMMIT();

    for (int kt = 0; kt < nk; kt++) {
        CP_WAIT1();
        __syncthreads();
        int s = kt % 3;
        uint32_t fb[4][2];
#pragma unroll
        for (int p = 0; p < 2; p++) {
            int krow = (lt & 1) * 8 + lr;
            int chIdx = (warp_n >> 3) + p * 2 + (lt >> 1);
            uint32_t addr = smem_u32(&Bsh[s][krow][4 * (chIdx ^ ((krow & 7) * 2))]);
            ldsm4t(fb[2 * p][0], fb[2 * p][1], fb[2 * p + 1][0], fb[2 * p + 1][1], addr);
        }
#pragma unroll
        for (int mt = 0; mt < MT; mt++) {
            int row = warp_m + mt * 16 + (lt & 1) * 8 + lr;
            uint32_t addr = smem_u32(&Ash[s][row][((lt >> 1) * 4) ^ (row & 4)]);
            uint32_t fa[4];
            ldsm4(fa[0], fa[1], fa[2], fa[3], addr);
#pragma unroll
            for (int nt = 0; nt < 4; nt++) mma16(acc[mt][nt], fa, fb[nt]);
        }
        if (kt + 2 < nk) load_stage(kt + 2, (kt + 2) % 3);
        CP_COMMIT();
    }

#pragma unroll
    for (int mt = 0; mt < MT; mt++)
#pragma unroll
        for (int nt = 0; nt < 4; nt++) {
            int row = by * CTAM + warp_m + mt * 16 + mq;
            int col = bx * 128 + warp_n + nt * 8 + kq * 2;
            float v0 = acc[mt][nt][0], v1 = acc[mt][nt][1];
            float v2 = acc[mt][nt][2], v3 = acc[mt][nt][3];
            if (EPI >= 1) {
                float b0 = bias[col], b1 = bias[col + 1];
                v0 += b0; v1 += b1; v2 += b0; v3 += b1;
            }
            if (EPI == 2) {
                v0 = gelu_f(v0); v1 = gelu_f(v1); v2 = gelu_f(v2); v3 = gelu_f(v3);
            }
            if (OF32) {
                *(float2*)(Cf + (size_t)row * N + col) = make_float2(v0, v1);
                *(float2*)(Cf + (size_t)(row + 8) * N + col) = make_float2(v2, v3);
            }
            if (OSPL) {
                size_t o = (size_t)row * (N >> 1) + (col >> 1);
                Ch[o] = cvt_pair(v0, v1);
                o = (size_t)(row + 8) * (N >> 1) + (col >> 1);
                Ch[o] = cvt_pair(v2, v3);
            }
        }
}

// ---------------- rank-32 expansion from fp16 T; Q/K/V all tok-major ----------------
__launch_bounds__(256)
__global__ void qkv2_k(const float* __restrict__ Vq, const float* __restrict__ Vk,
                       const float* __restrict__ Vv, const float* __restrict__ bq,
                       const float* __restrict__ bk, const float* __restrict__ bv) {
    __shared__ float Vs[RAz][DHz];
    __shared__ float tile[8][65];
    int z = blockIdx.y, j = blockIdx.z;
    int b = z / Hz, h = z % Hz;
    const float* Vm = (j == 0) ? Vq : ((j == 1) ? Vk : Vv);
    const float* bm = (j == 0) ? bq : ((j == 1) ? bk : bv);
    int tid = threadIdx.x;
#pragma unroll
    for (int i = 0; i < 8; i++) {
        int idx = tid + i * 256;
        Vs[idx >> 6][idx & 63] = Vm[(size_t)h * RAz * DHz + idx];
    }
    __syncthreads();

    int m0 = blockIdx.x * 8;
    int d = tid & 63, ml = tid >> 6;
#pragma unroll
    for (int rr = 0; rr < 2; rr++) {
        int r = ml + rr * 4;
        int m = m0 + r;
        const uint32_t* trow = g_Th + (size_t)(b * Mz + m) * 768 + j * 256 + h * 16;
        float acc = bm[h * DHz + d];
#pragma unroll
        for (int kp = 0; kp < 16; kp++) {
            __half2 hv = *(const __half2*)&trow[kp];
            float2 f = __half22float2(hv);
            acc += f.x * Vs[2 * kp][d] + f.y * Vs[2 * kp + 1][d];
        }
        tile[r][d] = acc;
    }
    __syncthreads();

    int m = tid >> 5, dp = tid & 31;
    float v0 = tile[m][2 * dp], v1 = tile[m][2 * dp + 1];
    uint32_t* dst = (j == 0) ? g_Qh : ((j == 1) ? g_Kh : g_Vh);
    if (j == 0) { v0 *= 0.125f; v1 *= 0.125f; }
    size_t o = ((size_t)z * Mz + m0 + m) * 32 + dp;
    dst[o] = cvt_pair(v0, v1);
}

// =====================================================================
// Fused flash attention (R16 version — tok-major K, scale folded into Q).
// =====================================================================
#define FLASH_SMEM_BYTES 83968
__launch_bounds__(256, 1)
__global__ void hflash(const float* __restrict__ mask) {
    extern __shared__ uint32_t dsm[];
    uint32_t* Qh = dsm;                               // [128][32]
    uint32_t* Khs[2] = {dsm + 4096,  dsm + 8192};     // [128 tok][32 u32] each
    uint32_t* Vhs[2] = {dsm + 12288, dsm + 16384};    // [128 tok][32 u32] each
    float* mk = (float*)(dsm + 20480);                // [512]

    int tid = threadIdx.x, lane = tid & 31, w = tid >> 5;
    int mq = lane >> 2, kq = lane & 3;
    int lt = lane >> 3, lr = lane & 7;
    int by = blockIdx.x, z = blockIdx.y;
    int b = z >> 4, h = z & 15;

    const uint32_t* Qhb = g_Qh + (size_t)z * Mz * 32;
    const uint32_t* Khb = g_Kh + (size_t)z * Mz * 32;
    const uint32_t* Vhb = g_Vh + (size_t)z * Mz * 32;

    {
        float2 mv = *(const float2*)(mask + (size_t)b * Mz + tid * 2);
        *(float2*)(mk + tid * 2) = mv;
    }

    auto load_kv = [&](int j, int s) {
#pragma unroll
        for (int i = 0; i < 4; i++) {
            int g = tid + i * 256;
            int row = g >> 3, ch = g & 7;
            int cc = ch ^ (row & 7);
            cp16(smem_u32(&Khs[s][row * 32 + cc * 4]),
                 Khb + (size_t)(j * 128 + row) * 32 + ch * 4);
        }
#pragma unroll
        for (int i = 0; i < 4; i++) {
            int g = tid + i * 256;
            int row = g >> 3, ch = g & 7;
            int cc = ch ^ (row & 7);
            cp16(smem_u32(&Vhs[s][row * 32 + cc * 4]),
                 Vhb + (size_t)(j * 128 + row) * 32 + ch * 4);
        }
    };

#pragma unroll
    for (int i = 0; i < 4; i++) {
        int g = tid + i * 256;
        int row = g >> 3, q0 = (g & 7) * 4;
        int cc = q0 ^ ((row & 7) * 4);
        size_t so = (size_t)(by * 128 + row) * 32 + q0;
        cp16(smem_u32(&Qh[row * 32 + cc]), Qhb + so);
    }
    load_kv(0, 0); CP_COMMIT();
    load_kv(1, 1); CP_COMMIT();

    float sacc[16][4];
    float oacc[8][4];
#pragma unroll
    for (int i = 0; i < 8; i++)
#pragma unroll
        for (int t = 0; t < 4; t++) oacc[i][t] = 0.f;
    float rmax0 = -1e30f, rmax1 = -1e30f;
    float rsum0 = 0.f, rsum1 = 0.f;
    uint32_t qh[4][4];

    for (int j = 0; j < 4; j++) {
        CP_WAIT1();
        __syncthreads();
        int s = j & 1;
        if (j == 0) {
            int r0 = w * 16 + mq, r1 = r0 + 8;
#pragma unroll
            for (int c = 0; c < 4; c++) {
                int p0 = (c * 8 + kq) ^ (mq * 4);
                int p1 = (c * 8 + 4 + kq) ^ (mq * 4);
                qh[c][0] = Qh[r0 * 32 + p0];
                qh[c][1] = Qh[r1 * 32 + p0];
                qh[c][2] = Qh[r0 * 32 + p1];
                qh[c][3] = Qh[r1 * 32 + p1];
            }
        }
        // ---- S = Q K^T (ldsm4 non-trans on tok-major K) ----
#pragma unroll
        for (int nt = 0; nt < 16; nt++)
#pragma unroll
            for (int t = 0; t < 4; t++) sacc[nt][t] = 0.f;
#pragma unroll
        for (int c = 0; c < 4; c++) {
#pragma unroll
            for (int ntp = 0; ntp < 8; ntp++) {
                int tokrow = ntp * 16 + (lt & 1) * 8 + lr;
                int chk = c * 2 + (lt >> 1);
                uint32_t addr = smem_u32(&Khs[s][tokrow * 32 + 4 * (chk ^ (tokrow & 7))]);
                uint32_t b0, b1, b2, b3;
                ldsm4(b0, b1, b2, b3, addr);
                uint32_t fb0[2] = {b0, b2}, fb1[2] = {b1, b3};
                mma16(sacc[2 * ntp], qh[c], fb0);
                mma16(sacc[2 * ntp + 1], qh[c], fb1);
            }
        }
        // ---- mask + online softmax (scale pre-folded into Q) ----
        float tm0 = -1e30f, tm1 = -1e30f;
#pragma unroll
        for (int nt = 0; nt < 16; nt++) {
            int n0 = j * 128 + nt * 8 + kq * 2;
            float m0 = mk[n0], m1 = mk[n0 + 1];
            sacc[nt][0] += m0;
            sacc[nt][1] += m1;
            sacc[nt][2] += m0;
            sacc[nt][3] += m1;
            tm0 = fmaxf(tm0, fmaxf(sacc[nt][0], sacc[nt][1]));
            tm1 = fmaxf(tm1, fmaxf(sacc[nt][2], sacc[nt][3]));
        }
        tm0 = fmaxf(tm0, __shfl_xor_sync(0xffffffffu, tm0, 1));
        tm0 = fmaxf(tm0, __shfl_xor_sync(0xffffffffu, tm0, 2));
        tm1 = fmaxf(tm1, __shfl_xor_sync(0xffffffffu, tm1, 1));
        tm1 = fmaxf(tm1, __shfl_xor_sync(0xffffffffu, tm1, 2));
        float nm0 = fmaxf(rmax0, tm0), nm1 = fmaxf(rmax1, tm1);
        float f0 = __expf(rmax0 - nm0), f1 = __expf(rmax1 - nm1);
        rmax0 = nm0; rmax1 = nm1;
        rsum0 *= f0; rsum1 *= f1;
#pragma unroll
        for (int nt = 0; nt < 8; nt++) {
            oacc[nt][0] *= f0; oacc[nt][1] *= f0;
            oacc[nt][2] *= f1; oacc[nt][3] *= f1;
        }
        float ps0 = 0.f, ps1 = 0.f;
#pragma unroll
        for (int nt = 0; nt < 16; nt++) {
            sacc[nt][0] = __expf(sacc[nt][0] - nm0);
            sacc[nt][1] = __expf(sacc[nt][1] - nm0);
            sacc[nt][2] = __expf(sacc[nt][2] - nm1);
            sacc[nt][3] = __expf(sacc[nt][3] - nm1);
            ps0 += sacc[nt][0] + sacc[nt][1];
            ps1 += sacc[nt][2] + sacc[nt][3];
        }
        rsum0 += ps0; rsum1 += ps1;
        // ---- O += P V (ldsm4t on tok-major V) ----
#pragma unroll
        for (int cc = 0; cc < 8; cc++) {
            uint32_t pah[4];
            pah[0] = cvt_pair(sacc[2 * cc][0],     sacc[2 * cc][1]);
            pah[1] = cvt_pair(sacc[2 * cc][2],     sacc[2 * cc][3]);
            pah[2] = cvt_pair(sacc[2 * cc + 1][0], sacc[2 * cc + 1][1]);
            pah[3] = cvt_pair(sacc[2 * cc + 1][2], sacc[2 * cc + 1][3]);
#pragma unroll
            for (int ntp = 0; ntp < 4; ntp++) {
                int trow = cc * 16 + (lt & 1) * 8 + lr;
                int chk = ntp * 2 + (lt >> 1);
                uint32_t addr = smem_u32(&Vhs[s][trow * 32 + 4 * (chk ^ (trow & 7))]);
                uint32_t b0, b1, b2, b3;
                ldsm4t(b0, b1, b2, b3, addr);
                uint32_t fb0[2] = {b0, b1}, fb1[2] = {b2, b3};
                mma16(oacc[2 * ntp], pah, fb0);
                mma16(oacc[2 * ntp + 1], pah, fb1);
            }
        }
        __syncthreads();
        if (j + 2 < 4) load_kv(j + 2, s);
        CP_COMMIT();
    }

    // ---- epilogue ----
    rsum0 += __shfl_xor_sync(0xffffffffu, rsum0, 1);
    rsum0 += __shfl_xor_sync(0xffffffffu, rsum0, 2);
    rsum1 += __shfl_xor_sync(0xffffffffu, rsum1, 1);
    rsum1 += __shfl_xor_sync(0xffffffffu, rsum1, 2);
    float inv0 = 1.0f / rsum0, inv1 = 1.0f / rsum1;
    int m0 = by * 128 + w * 16 + mq;
#pragma unroll
    for (int nt = 0; nt < 8; nt++) {
        int d = nt * 8 + kq * 2;
        int colp = (h * DHz + d) >> 1;
        size_t o = (size_t)(b * Mz + m0) * 512 + colp;
        g_ath[o] = cvt_pair(oacc[nt][0] * inv0, oacc[nt][1] * inv0);
        o = (size_t)(b * Mz + m0 + 8) * 512 + colp;
        g_ath[o] = cvt_pair(oacc[nt][2] * inv1, oacc[nt][3] * inv1);
    }
}

// ---------------- residual + LayerNorm ----------------
template <bool SPLIT>
__launch_bounds__(256)
__global__ void ln_k(const float* __restrict__ a, const float* __restrict__ r,
                     const float* __restrict__ g, const float* __restrict__ bb,
                     float* __restrict__ out) {
    __shared__ float sh[8];
    int row = blockIdx.x;
    int tid = threadIdx.x;
    int lane = tid & 31, warp = tid >> 5;
    int c = tid * 4;
    float4 xa = *(const float4*)(a + (size_t)row * DMz + c);
    float4 ya = *(const float4*)(r + (size_t)row * DMz + c);
    float v[4] = {xa.x + ya.x, xa.y + ya.y, xa.z + ya.z, xa.w + ya.w};
    float s = v[0] + v[1] + v[2] + v[3];
#pragma unroll
    for (int o = 16; o > 0; o >>= 1) s += __shfl_xor_sync(0xffffffffu, s, o);
    if (lane == 0) sh[warp] = s;
    __syncthreads();
    if (warp == 0) {
        float t = (lane < 8) ? sh[lane] : 0.f;
#pragma unroll
        for (int o = 4; o > 0; o >>= 1) t += __shfl_xor_sync(0xffffffffu, t, o);
        if (lane == 0) sh[0] = t;
    }
    __syncthreads();
    float mu = sh[0] * (1.0f / DMz);
    __syncthreads();

    float q = 0.f;
#pragma unroll
    for (int i = 0; i < 4; i++) {
        float d = v[i] - mu;
        q += d * d;
    }
#pragma unroll
    for (int o = 16; o > 0; o >>= 1) q += __shfl_xor_sync(0xffffffffu, q, o);
    if (lane == 0) sh[warp] = q;
    __syncthreads();
    if (warp == 0) {
        float t = (lane < 8) ? sh[lane] : 0.f;
#pragma unroll
        for (int o = 4; o > 0; o >>= 1) t += __shfl_xor_sync(0xffffffffu, t, o);
        if (lane == 0) sh[0] = t;
    }
    __syncthreads();
    float var = sh[0] * (1.0f / DMz);
    float rs = rsqrtf(var + LN_EPS);
    float4 gg = *(const float4*)(g + c);
    float4 bbv = *(const float4*)(bb + c);
    float o0 = (v[0] - mu) * rs * gg.x + bbv.x;
    float o1 = (v[1] - mu) * rs * gg.y + bbv.y;
    float o2 = (v[2] - mu) * rs * gg.z + bbv.z;
    float o3 = (v[3] - mu) * rs * gg.w + bbv.w;
    *(float4*)(out + (size_t)row * DMz + c) = make_float4(o0, o1, o2, o3);
    if (SPLIT) {
        size_t o = (size_t)row * 512 + (c >> 1);
        g_x1h[o] = cvt_pair(o0, o1);
        g_x1h[o + 1] = cvt_pair(o2, o3);
    }
}

// ---------------- launch ----------------
extern "C" void kernel_launch(void* const* d_in, const int* in_sizes, int n_in,
                              void* d_out, int out_size) {
    const float* x    = (const float*)d_in[0];
    const float* mask = (const float*)d_in[1];
    const float* Pq   = (const float*)d_in[2];
    const float* Vq   = (const float*)d_in[3];
    const float* Pk   = (const float*)d_in[4];
    const float* Vk   = (const float*)d_in[5];
    const float* Pv   = (const float*)d_in[6];
    const float* Vv   = (const float*)d_in[7];
    const float* bq   = (const float*)d_in[8];
    const float* bk   = (const float*)d_in[9];
    const float* bv   = (const float*)d_in[10];
    const float* Uo   = (const float*)d_in[11];
    const float* Vo   = (const float*)d_in[12];
    const float* bo   = (const float*)d_in[13];
    const float* U1   = (const float*)d_in[14];
    const float* V1   = (const float*)d_in[15];
    const float* b1   = (const float*)d_in[16];
    const float* U2   = (const float*)d_in[17];
    const float* V2   = (const float*)d_in[18];
    const float* b2   = (const float*)d_in[19];
    const float* ln1g = (const float*)d_in[20];
    const float* ln1b = (const float*)d_in[21];
    const float* ln2g = (const float*)d_in[22];
    const float* ln2b = (const float*)d_in[23];
    float* out = (float*)d_out;

#define SYM(p, s) cudaGetSymbolAddress((void**)&p, s)
    uint32_t *xh, *wch, *Th, *Uoh, *Voh, *U1h, *V1h, *U2h, *V2h;
    uint32_t *ath, *t1h, *x1h, *mdh, *hdh, *t2h;
    float *y1, *x1, *y2;
    SYM(xh, g_xh); SYM(wch, g_wch); SYM(Th, g_Th);
    SYM(Uoh, g_Uoh); SYM(Voh, g_Voh);
    SYM(U1h, g_U1h); SYM(V1h, g_V1h);
    SYM(U2h, g_U2h); SYM(V2h, g_V2h);
    SYM(ath, g_ath); SYM(t1h, g_t1h);
    SYM(x1h, g_x1h); SYM(mdh, g_mdh);
    SYM(hdh, g_hdh); SYM(t2h, g_t2h);
    SYM(y1, g_y1); SYM(x1, g_x1); SYM(y2, g_y2);
#undef SYM

    cudaFuncSetAttribute(hflash, cudaFuncAttributeMaxDynamicSharedMemorySize,
                         FLASH_SMEM_BYTES);

    // operand conversion (3 launches)
    conv_x<<<BMr * 512 / 256, 256>>>(x);
    pack_w_split<<<DMz * (C3 / 2) / 256, 256>>>(Pq, Pk, Pv);
    convAll<<<(2359296 + 255) / 256, 256>>>(Uo, Vo, U1, V1, U2, V2);

    // qkv low-rank: GEMM writes T as fp16 pairs, then rank-32 expansion
    hgemm<128, false, true, 0><<<dim3(C3 / 128, BMr / 128), 256>>>(
        xh, wch, nullptr, Th, C3, DMz, nullptr);
    qkv2_k<<<dim3(Mz / 8, ZT, 3), 256>>>(Vq, Vk, Vv, bq, bk, bv);

    // fused attention
    hflash<<<dim3(Mz / 128, ZT), 256, FLASH_SMEM_BYTES>>>(mask);

    // output projection + LN1
    hgemm<64, false, true, 0><<<dim3(ROz / 128, BMr / 64), 256>>>(
        ath, Uoh, nullptr, t1h, ROz, DMz, nullptr);
    hgemm<128, true, false, 1><<<dim3(DMz / 128, BMr / 128), 256>>>(
        t1h, Voh, y1, nullptr, DMz, ROz, bo);
    ln_k<true><<<BMr, 256>>>(x, y1, ln1g, ln1b, x1);

    // FFN
    hgemm<64, false, true, 0><<<dim3(RFz / 128, BMr / 64), 256>>>(
        x1h, U1h, nullptr, mdh, RFz, DMz, nullptr);
    hgemm<128, false, true, 2><<<dim3(DFFz / 128, BMr / 128), 256>>>(
        mdh, V1h, nullptr, hdh, DFFz, RFz, b1);
    hgemm<64, false, true, 0><<<dim3(RFz / 128, BMr / 64), 256>>>(
        hdh, U2h, nullptr, t2h, RFz, DFFz, nullptr);
    hgemm<128, true, false, 1><<<dim3(DMz / 128, BMr / 128), 256>>>(
        t2h, V2h, y2, nullptr, DMz, RFz, b2);

    // LN2 -> out
    ln_k<false><<<BMr, 256>>>(x1, y2, ln2g, ln2b, out);
}